// round 6
// baseline (speedup 1.0000x reference)
#include <cuda_runtime.h>

#define N_NODES 100000
#define N_EDGES 1600000
#define H       128

// ---------------- scratch (device globals; no allocation allowed) ----------
__device__ __align__(16) float g_bufP[(size_t)N_NODES * H];
__device__ __align__(16) float g_bufQ[(size_t)N_NODES * H];
__device__ int   g_count[N_NODES];
__device__ int   g_off[N_NODES + 1];
__device__ int   g_csr[N_EDGES];
__device__ __align__(16) float g_sum[H];
__device__ __align__(16) float g_sumsq[H];
__device__ __align__(16) float g_scale[H];
__device__ __align__(16) float g_shift[H];
__device__ int   g_is64;   // edge_index dtype flag: 1 = int64 layout, 0 = int32

// compile-time buffer selector: 0=P, 1=Q
template <int S>
__device__ __forceinline__ float* BUF() { return (S == 0) ? g_bufP : g_bufQ; }

// edge accessors robust to int32 vs int64 storage of edge_index
__device__ __forceinline__ int edge_src(const int* __restrict__ ei32, int e, int is64) {
    return is64 ? ei32[2 * e] : ei32[e];
}
__device__ __forceinline__ int edge_dst(const int* __restrict__ ei32, int e, int is64) {
    return is64 ? ei32[2 * (N_EDGES + e)] : ei32[N_EDGES + e];
}

// ---------------- dtype detect + init --------------------------------------
__global__ void detect_kernel(const int* __restrict__ ei32) {
    __shared__ int nz;
    if (threadIdx.x == 0) nz = 0;
    __syncthreads();
    // int64 values < 2^31: odd 32-bit words are all zero. int32 data: odd words
    // are src-node ids (random in [0,1e5)); 256 of them all zero is impossible.
    int w = ei32[2 * threadIdx.x + 1];
    if (w != 0) atomicOr(&nz, 1);
    __syncthreads();
    if (threadIdx.x == 0) g_is64 = (nz == 0) ? 1 : 0;
}

__global__ void init_kernel() {
    int i = blockIdx.x * blockDim.x + threadIdx.x;
    if (i < N_NODES) g_count[i] = 0;
    if (i < H) { g_sum[i] = 0.f; g_sumsq[i] = 0.f; }
}

// ---------------- CSR build -------------------------------------------------
__global__ void hist_kernel(const int* __restrict__ ei32) {
    int e = blockIdx.x * blockDim.x + threadIdx.x;
    int is64 = g_is64;
    if (e < N_EDGES) atomicAdd(&g_count[edge_dst(ei32, e, is64)], 1);
}

__global__ void scan_kernel() {
    __shared__ int s[1024];
    int t = threadIdx.x;
    const int CH = (N_NODES + 1023) / 1024;  // 98
    int base = t * CH;
    int sum = 0;
    for (int i = 0; i < CH; i++) {
        int idx = base + i;
        if (idx < N_NODES) sum += g_count[idx];
    }
    s[t] = sum;
    __syncthreads();
    for (int off = 1; off < 1024; off <<= 1) {
        int v = 0;
        if (t >= off) v = s[t - off];
        __syncthreads();
        s[t] += v;
        __syncthreads();
    }
    int run = (t == 0) ? 0 : s[t - 1];   // exclusive prefix
    for (int i = 0; i < CH; i++) {
        int idx = base + i;
        if (idx < N_NODES) {
            g_off[idx]  = run;
            run += g_count[idx];
            g_count[idx] = g_off[idx];   // reuse as fill cursor
        }
    }
    if (t == 1023) g_off[N_NODES] = s[1023];
}

__global__ void fill_kernel(const int* __restrict__ ei32) {
    int e = blockIdx.x * blockDim.x + threadIdx.x;
    int is64 = g_is64;
    if (e < N_EDGES) {
        int d = edge_dst(ei32, e, is64);
        int p = atomicAdd(&g_count[d], 1);
        g_csr[p] = edge_src(ei32, e, is64);
    }
}

// ---------------- aggregation: dst = (1+eps)*X + sum_{j in nbr} X[j] --------
// SRCSEL == -1: read external pointer (layer 0 input x)
template <int D, int SRCSEL, int DSTSEL>
__global__ void aggregate_kernel(const float* __restrict__ Xext,
                                 const float* __restrict__ eps_p) {
    const float* X = (SRCSEL < 0) ? Xext : BUF<(SRCSEL < 0) ? 0 : SRCSEL>();
    float* out = BUF<DSTSEL>();
    int gw   = (blockIdx.x * blockDim.x + threadIdx.x) >> 5;  // warp per node
    int lane = threadIdx.x & 31;
    if (gw >= N_NODES) return;
    float epsv = 1.0f + eps_p[0];
    int s = g_off[gw], e = g_off[gw + 1];
    if (D == 128) {
        float4 acc = make_float4(0.f, 0.f, 0.f, 0.f);
        const float4* Xv = (const float4*)X;
        for (int t = s; t < e; t++) {
            int j = g_csr[t];
            float4 v = Xv[(size_t)j * 32 + lane];
            acc.x += v.x; acc.y += v.y; acc.z += v.z; acc.w += v.w;
        }
        float4 xv = Xv[(size_t)gw * 32 + lane];
        float4 o;
        o.x = fmaf(epsv, xv.x, acc.x);
        o.y = fmaf(epsv, xv.y, acc.y);
        o.z = fmaf(epsv, xv.z, acc.z);
        o.w = fmaf(epsv, xv.w, acc.w);
        ((float4*)out)[(size_t)gw * 32 + lane] = o;
    } else {  // D == 64
        float2 acc = make_float2(0.f, 0.f);
        const float2* Xv = (const float2*)X;
        for (int t = s; t < e; t++) {
            int j = g_csr[t];
            float2 v = Xv[(size_t)j * 32 + lane];
            acc.x += v.x; acc.y += v.y;
        }
        float2 xv = Xv[(size_t)gw * 32 + lane];
        float2 o;
        o.x = fmaf(epsv, xv.x, acc.x);
        o.y = fmaf(epsv, xv.y, acc.y);
        ((float2*)out)[(size_t)gw * 32 + lane] = o;
    }
}

// ---------------- SGEMM: C[M,128] = op(A[M,K]) @ B[K,128] (+bias, relu) -----
// TRANS_A: apply per-K-column BN scale/shift + relu on A load (fused BN+relu)
template <int ASEL, int CSEL, bool TRANS_A, bool RELU_OUT>
__global__ __launch_bounds__(256)
void sgemm_kernel(const float* __restrict__ B,
                  const float* __restrict__ bias, int K) {
    const float* A = BUF<ASEL>();
    float* C = BUF<CSEL>();
    const int M = N_NODES;
    __shared__ float As[16][132];  // transposed: As[k][m], padded
    __shared__ float Bs[16][132];  // Bs[k][n], padded
    int tid = threadIdx.x;
    int blockRow = blockIdx.x * 128;
    int tx = tid & 15;   // along N
    int ty = tid >> 4;   // along M
    float acc[8][8];
#pragma unroll
    for (int m = 0; m < 8; m++)
#pragma unroll
        for (int n = 0; n < 8; n++) acc[m][n] = 0.f;

    for (int k0 = 0; k0 < K; k0 += 16) {
        // A tile: 128 rows x 16 cols, float4 per load, 2 loads per thread
#pragma unroll
        for (int i = 0; i < 2; i++) {
            int f = tid + i * 256;
            int r = f >> 2;
            int c = (f & 3) * 4;
            int grow = blockRow + r;
            float4 v = make_float4(0.f, 0.f, 0.f, 0.f);
            if (grow < M) v = *(const float4*)(A + (size_t)grow * K + k0 + c);
            if (TRANS_A) {
                float4 sc = *(const float4*)(g_scale + k0 + c);
                float4 sh = *(const float4*)(g_shift + k0 + c);
                v.x = fmaxf(fmaf(v.x, sc.x, sh.x), 0.f);
                v.y = fmaxf(fmaf(v.y, sc.y, sh.y), 0.f);
                v.z = fmaxf(fmaf(v.z, sc.z, sh.z), 0.f);
                v.w = fmaxf(fmaf(v.w, sc.w, sh.w), 0.f);
            }
            As[c + 0][r] = v.x;
            As[c + 1][r] = v.y;
            As[c + 2][r] = v.z;
            As[c + 3][r] = v.w;
        }
        // B tile: 16 rows x 128 cols
#pragma unroll
        for (int i = 0; i < 2; i++) {
            int f = tid + i * 256;
            int r = f >> 5;
            int c = (f & 31) * 4;
            *(float4*)&Bs[r][c] = *(const float4*)(B + (size_t)(k0 + r) * 128 + c);
        }
        __syncthreads();
#pragma unroll
        for (int k = 0; k < 16; k++) {
            float aR[8], bR[8];
#pragma unroll
            for (int m = 0; m < 8; m++) aR[m] = As[k][ty * 8 + m];
#pragma unroll
            for (int n = 0; n < 8; n++) bR[n] = Bs[k][tx * 8 + n];
#pragma unroll
            for (int m = 0; m < 8; m++)
#pragma unroll
                for (int n = 0; n < 8; n++)
                    acc[m][n] = fmaf(aR[m], bR[n], acc[m][n]);
        }
        __syncthreads();
    }
#pragma unroll
    for (int m = 0; m < 8; m++) {
        int grow = blockRow + ty * 8 + m;
        if (grow >= M) continue;
#pragma unroll
        for (int n = 0; n < 8; n += 4) {
            int gc = tx * 8 + n;
            float4 b4 = *(const float4*)(bias + gc);
            float4 o;
            o.x = acc[m][n + 0] + b4.x;
            o.y = acc[m][n + 1] + b4.y;
            o.z = acc[m][n + 2] + b4.z;
            o.w = acc[m][n + 3] + b4.w;
            if (RELU_OUT) {
                o.x = fmaxf(o.x, 0.f); o.y = fmaxf(o.y, 0.f);
                o.z = fmaxf(o.z, 0.f); o.w = fmaxf(o.w, 0.f);
            }
            *(float4*)(C + (size_t)grow * 128 + gc) = o;
        }
    }
}

// ---------------- BatchNorm batch statistics --------------------------------
template <int ZSEL>
__global__ void bn_stats_kernel() {
    const float* Z = BUF<ZSEL>();
    int c = threadIdx.x;  // 128 channels
    float s = 0.f, s2 = 0.f;
    for (int r = blockIdx.x; r < N_NODES; r += gridDim.x) {
        float v = Z[(size_t)r * H + c];
        s += v;
        s2 += v * v;
    }
    atomicAdd(&g_sum[c], s);
    atomicAdd(&g_sumsq[c], s2);
}

__global__ void bn_finalize_kernel(const float* __restrict__ g,
                                   const float* __restrict__ be) {
    int c = threadIdx.x;
    float mu  = g_sum[c] * (1.0f / N_NODES);
    float var = g_sumsq[c] * (1.0f / N_NODES) - mu * mu;
    float sc  = g[c] * rsqrtf(var + 1e-5f);
    g_scale[c] = sc;
    g_shift[c] = be[c] - mu * sc;
    g_sum[c] = 0.f;    // reset so the captured graph is replayable
    g_sumsq[c] = 0.f;
}

// ---------------- head: out[i,o] = T(row, relu'd already) @ hwb + hbb -------
__global__ void head_kernel(const float* __restrict__ W,
                            const float* __restrict__ b, float* __restrict__ out) {
    const float* T = BUF<1>();
    int gw   = (blockIdx.x * blockDim.x + threadIdx.x) >> 5;  // warp per node
    int lane = threadIdx.x & 31;
    if (gw >= N_NODES) return;
    float4 t  = ((const float4*)T)[(size_t)gw * 32 + lane];
    // W: [128,2] row-major; k = lane*4 + q -> floats W[lane*8 .. lane*8+7]
    float4 w0 = ((const float4*)W)[lane * 2];      // (k0o0, k0o1, k1o0, k1o1)
    float4 w1 = ((const float4*)W)[lane * 2 + 1];  // (k2o0, k2o1, k3o0, k3o1)
    float a0 = t.x * w0.x + t.y * w0.z + t.z * w1.x + t.w * w1.z;
    float a1 = t.x * w0.y + t.y * w0.w + t.z * w1.y + t.w * w1.w;
#pragma unroll
    for (int o = 16; o > 0; o >>= 1) {
        a0 += __shfl_xor_sync(0xffffffffu, a0, o);
        a1 += __shfl_xor_sync(0xffffffffu, a1, o);
    }
    if (lane == 0) {
        out[(size_t)gw * 2 + 0] = a0 + b[0];
        out[(size_t)gw * 2 + 1] = a1 + b[1];
    }
}

// ---------------- launch -----------------------------------------------------
extern "C" void kernel_launch(void* const* d_in, const int* in_sizes, int n_in,
                              void* d_out, int out_size) {
    const float* x    = (const float*)d_in[0];
    const int*   ei32 = (const int*)d_in[1];   // int32 OR int64 (detected on device)
    const float* w0a = (const float*)d_in[2];
    const float* b0a = (const float*)d_in[3];
    const float* g0  = (const float*)d_in[4];
    const float* be0 = (const float*)d_in[5];
    const float* w0b = (const float*)d_in[6];
    const float* b0b = (const float*)d_in[7];
    const float* ep0 = (const float*)d_in[8];
    const float* w1a = (const float*)d_in[9];
    const float* b1a = (const float*)d_in[10];
    const float* g1  = (const float*)d_in[11];
    const float* be1 = (const float*)d_in[12];
    const float* w1b = (const float*)d_in[13];
    const float* b1b = (const float*)d_in[14];
    const float* ep1 = (const float*)d_in[15];
    const float* w2a = (const float*)d_in[16];
    const float* b2a = (const float*)d_in[17];
    const float* g2  = (const float*)d_in[18];
    const float* be2 = (const float*)d_in[19];
    const float* w2b = (const float*)d_in[20];
    const float* b2b = (const float*)d_in[21];
    const float* ep2 = (const float*)d_in[22];
    const float* hwa = (const float*)d_in[23];
    const float* hba = (const float*)d_in[24];
    const float* hwb = (const float*)d_in[25];
    const float* hbb = (const float*)d_in[26];
    float* out = (float*)d_out;

    const int edgeBlocks = (N_EDGES + 255) / 256;
    const int nodeBlocks = (N_NODES + 255) / 256;
    const int warpBlocks = (N_NODES * 32 + 255) / 256;  // warp-per-node kernels
    const int gemmBlocks = (N_NODES + 127) / 128;

    // CSR by dst (built once per launch; reused by all 3 layers)
    detect_kernel<<<1, 256>>>(ei32);
    init_kernel<<<nodeBlocks, 256>>>();
    hist_kernel<<<edgeBlocks, 256>>>(ei32);
    scan_kernel<<<1, 1024>>>();
    fill_kernel<<<edgeBlocks, 256>>>(ei32);

    // ---- layer 0 (D_in = 64): x -> P -> Q -> P ----
    aggregate_kernel<64, -1, 0><<<warpBlocks, 256>>>(x, ep0);
    sgemm_kernel<0, 1, false, false><<<gemmBlocks, 256>>>(w0a, b0a, 64);
    bn_stats_kernel<1><<<512, 128>>>();
    bn_finalize_kernel<<<1, 128>>>(g0, be0);
    sgemm_kernel<1, 0, true, true><<<gemmBlocks, 256>>>(w0b, b0b, 128);

    // ---- layer 1: P -> Q -> P -> Q ----
    aggregate_kernel<128, 0, 1><<<warpBlocks, 256>>>(nullptr, ep1);
    sgemm_kernel<1, 0, false, false><<<gemmBlocks, 256>>>(w1a, b1a, 128);
    bn_stats_kernel<0><<<512, 128>>>();
    bn_finalize_kernel<<<1, 128>>>(g1, be1);
    sgemm_kernel<0, 1, true, true><<<gemmBlocks, 256>>>(w1b, b1b, 128);

    // ---- layer 2: Q -> P -> Q -> P ----
    aggregate_kernel<128, 1, 0><<<warpBlocks, 256>>>(nullptr, ep2);
    sgemm_kernel<0, 1, false, false><<<gemmBlocks, 256>>>(w2a, b2a, 128);
    bn_stats_kernel<1><<<512, 128>>>();
    bn_finalize_kernel<<<1, 128>>>(g2, be2);
    sgemm_kernel<1, 0, true, true><<<gemmBlocks, 256>>>(w2b, b2b, 128);

    // ---- head: relu(P@hwa+hba) -> Q; Q@hwb+hbb -> out ----
    sgemm_kernel<0, 1, false, true><<<gemmBlocks, 256>>>(hwa, hba, 128);
    head_kernel<<<warpBlocks, 256>>>(hwb, hbb, out);
}

// round 8
// speedup vs baseline: 1.2649x; 1.2649x over previous
#include <cuda_runtime.h>

#define N_NODES 100000
#define N_EDGES 1600000
#define H       128
#define NPAD    102400              // 25 * 4096, padded for guard-free int4 scan

// ---------------- scratch (device globals; no allocation allowed) ----------
__device__ __align__(16) float g_bufP[(size_t)N_NODES * H];
__device__ __align__(16) float g_bufQ[(size_t)N_NODES * H];
__device__ __align__(16) int   g_count[NPAD];        // histogram, then fill-cursor
__device__ __align__(16) int   g_off[NPAD + 4];      // CSR row offsets (padded)
__device__ int   g_part[32];                         // per-block scan partials
__device__ int   g_csr[N_EDGES];
__device__ __align__(16) float g_sum[H];
__device__ __align__(16) float g_sumsq[H];
__device__ __align__(16) float g_scale[H];
__device__ __align__(16) float g_shift[H];
__device__ int   g_is64;   // edge_index dtype flag: 1 = int64 layout, 0 = int32

// compile-time buffer selector: 0=P, 1=Q
template <int S>
__device__ __forceinline__ float* BUF() { return (S == 0) ? g_bufP : g_bufQ; }

// edge accessors robust to int32 vs int64 storage of edge_index
__device__ __forceinline__ int edge_src(const int* __restrict__ ei32, int e, int is64) {
    return is64 ? ei32[2 * e] : ei32[e];
}
__device__ __forceinline__ int edge_dst(const int* __restrict__ ei32, int e, int is64) {
    return is64 ? ei32[2 * (N_EDGES + e)] : ei32[N_EDGES + e];
}

// ---------------- dtype detect + init --------------------------------------
__global__ void detect_kernel(const int* __restrict__ ei32) {
    __shared__ int nz;
    if (threadIdx.x == 0) nz = 0;
    __syncthreads();
    // int64 values < 2^31: odd 32-bit words are all zero. int32 data: odd words
    // are node ids (random in [0,1e5)); 256 of them all zero is impossible.
    int w = ei32[2 * threadIdx.x + 1];
    if (w != 0) atomicOr(&nz, 1);
    __syncthreads();
    if (threadIdx.x == 0) g_is64 = (nz == 0) ? 1 : 0;
}

__global__ void init_kernel() {
    int i = blockIdx.x * blockDim.x + threadIdx.x;
    if (i < NPAD) g_count[i] = 0;
    if (i < H) { g_sum[i] = 0.f; g_sumsq[i] = 0.f; }
}

// ---------------- CSR build -------------------------------------------------
__global__ void hist_kernel(const int* __restrict__ ei32) {
    int e = blockIdx.x * blockDim.x + threadIdx.x;
    int is64 = g_is64;
    if (e < N_EDGES) atomicAdd(&g_count[edge_dst(ei32, e, is64)], 1);
}

// phase 1: per-block (4096 elems) exclusive scan into g_off + block total
__global__ void scan1_kernel() {
    __shared__ int wsum[32];
    int b = blockIdx.x, t = threadIdx.x;
    int base = b * 4096 + t * 4;
    int4 v = *(const int4*)&g_count[base];
    int s0 = v.x, s1 = s0 + v.y, s2 = s1 + v.z, s3 = s2 + v.w;  // inclusive in-thread
    int lane = t & 31, wid = t >> 5;
    int x = s3;
#pragma unroll
    for (int o = 1; o < 32; o <<= 1) {
        int y = __shfl_up_sync(0xffffffffu, x, o);
        if (lane >= o) x += y;
    }
    if (lane == 31) wsum[wid] = x;
    __syncthreads();
    if (wid == 0) {
        int w = wsum[lane];
#pragma unroll
        for (int o = 1; o < 32; o <<= 1) {
            int y = __shfl_up_sync(0xffffffffu, w, o);
            if (lane >= o) w += y;
        }
        wsum[lane] = w;
    }
    __syncthreads();
    int warpoff = (wid == 0) ? 0 : wsum[wid - 1];
    int texc = warpoff + x - s3;      // exclusive prefix for this thread
    int4 o4;
    o4.x = texc; o4.y = texc + s0; o4.z = texc + s1; o4.w = texc + s2;
    *(int4*)&g_off[base] = o4;
    if (t == 1023) g_part[b] = warpoff + x;   // block total
}

// phase 2: exclusive scan of 25 block totals (one warp)
__global__ void scan2_kernel() {
    int lane = threadIdx.x;
    int v = (lane < 25) ? g_part[lane] : 0;
    int x = v;
#pragma unroll
    for (int o = 1; o < 32; o <<= 1) {
        int y = __shfl_up_sync(0xffffffffu, x, o);
        if (lane >= o) x += y;
    }
    if (lane < 25) g_part[lane] = x - v;   // exclusive
}

// phase 3: add block bases; also copy to g_count as the fill cursor
__global__ void scan3_kernel() {
    int i4 = (blockIdx.x * blockDim.x + threadIdx.x) * 4;   // 100 blocks x 256
    int add = g_part[i4 >> 12];
    int4 v = *(const int4*)&g_off[i4];
    v.x += add; v.y += add; v.z += add; v.w += add;
    *(int4*)&g_off[i4] = v;
    *(int4*)&g_count[i4] = v;
}

__global__ void fill_kernel(const int* __restrict__ ei32) {
    int e = blockIdx.x * blockDim.x + threadIdx.x;
    int is64 = g_is64;
    if (e < N_EDGES) {
        int d = edge_dst(ei32, e, is64);
        int p = atomicAdd(&g_count[d], 1);
        g_csr[p] = edge_src(ei32, e, is64);
    }
}

// ---------------- aggregation: dst = (1+eps)*X + sum_{j in nbr} X[j] --------
// SRCSEL == -1: read external pointer (layer 0 input x)
template <int D, int SRCSEL, int DSTSEL>
__global__ void aggregate_kernel(const float* __restrict__ Xext,
                                 const float* __restrict__ eps_p) {
    const float* X = (SRCSEL < 0) ? Xext : BUF<(SRCSEL < 0) ? 0 : SRCSEL>();
    float* out = BUF<DSTSEL>();
    int gw   = (blockIdx.x * blockDim.x + threadIdx.x) >> 5;  // warp per node
    int lane = threadIdx.x & 31;
    if (gw >= N_NODES) return;
    float epsv = 1.0f + eps_p[0];
    int s = g_off[gw], e = g_off[gw + 1];
    if (D == 128) {
        float4 acc = make_float4(0.f, 0.f, 0.f, 0.f);
        const float4* Xv = (const float4*)X;
        for (int t = s; t < e; t++) {
            int j = g_csr[t];
            float4 v = Xv[(size_t)j * 32 + lane];
            acc.x += v.x; acc.y += v.y; acc.z += v.z; acc.w += v.w;
        }
        float4 xv = Xv[(size_t)gw * 32 + lane];
        float4 o;
        o.x = fmaf(epsv, xv.x, acc.x);
        o.y = fmaf(epsv, xv.y, acc.y);
        o.z = fmaf(epsv, xv.z, acc.z);
        o.w = fmaf(epsv, xv.w, acc.w);
        ((float4*)out)[(size_t)gw * 32 + lane] = o;
    } else {  // D == 64
        float2 acc = make_float2(0.f, 0.f);
        const float2* Xv = (const float2*)X;
        for (int t = s; t < e; t++) {
            int j = g_csr[t];
            float2 v = Xv[(size_t)j * 32 + lane];
            acc.x += v.x; acc.y += v.y;
        }
        float2 xv = Xv[(size_t)gw * 32 + lane];
        float2 o;
        o.x = fmaf(epsv, xv.x, acc.x);
        o.y = fmaf(epsv, xv.y, acc.y);
        ((float2*)out)[(size_t)gw * 32 + lane] = o;
    }
}

// ---------------- SGEMM: C[M,128] = op(A[M,K]) @ B[K,128] (+bias, relu) -----
// TRANS_A: apply per-K-column BN scale/shift + relu on A load (fused BN+relu)
// STATS:   accumulate column sum/sumsq of C into g_sum/g_sumsq (fused BN stats)
template <int ASEL, int CSEL, bool TRANS_A, bool RELU_OUT, bool STATS>
__global__ __launch_bounds__(256)
void sgemm_kernel(const float* __restrict__ B,
                  const float* __restrict__ bias, int K) {
    const float* A = BUF<ASEL>();
    float* C = BUF<CSEL>();
    const int M = N_NODES;
    __shared__ float sm[4224];                 // As: [0,2112) Bs: [2112,4224)
#define AS(k, i) sm[(k) * 132 + (i)]
#define BS(k, i) sm[2112 + (k) * 132 + (i)]
    int tid = threadIdx.x;
    int blockRow = blockIdx.x * 128;
    int tx = tid & 15;   // along N
    int ty = tid >> 4;   // along M
    float acc[8][8];
#pragma unroll
    for (int m = 0; m < 8; m++)
#pragma unroll
        for (int n = 0; n < 8; n++) acc[m][n] = 0.f;

    for (int k0 = 0; k0 < K; k0 += 16) {
        // A tile: 128 rows x 16 cols, float4 per load, 2 loads per thread
#pragma unroll
        for (int i = 0; i < 2; i++) {
            int f = tid + i * 256;
            int r = f >> 2;
            int c = (f & 3) * 4;
            int grow = blockRow + r;
            float4 v = make_float4(0.f, 0.f, 0.f, 0.f);
            if (grow < M) v = *(const float4*)(A + (size_t)grow * K + k0 + c);
            if (TRANS_A) {
                float4 sc = *(const float4*)(g_scale + k0 + c);
                float4 sh = *(const float4*)(g_shift + k0 + c);
                v.x = fmaxf(fmaf(v.x, sc.x, sh.x), 0.f);
                v.y = fmaxf(fmaf(v.y, sc.y, sh.y), 0.f);
                v.z = fmaxf(fmaf(v.z, sc.z, sh.z), 0.f);
                v.w = fmaxf(fmaf(v.w, sc.w, sh.w), 0.f);
            }
            AS(c + 0, r) = v.x;
            AS(c + 1, r) = v.y;
            AS(c + 2, r) = v.z;
            AS(c + 3, r) = v.w;
        }
        // B tile: 16 rows x 128 cols
#pragma unroll
        for (int i = 0; i < 2; i++) {
            int f = tid + i * 256;
            int r = f >> 5;
            int c = (f & 31) * 4;
            *(float4*)&BS(r, c) = *(const float4*)(B + (size_t)(k0 + r) * 128 + c);
        }
        __syncthreads();
#pragma unroll
        for (int k = 0; k < 16; k++) {
            float aR[8], bR[8];
#pragma unroll
            for (int m = 0; m < 8; m++) aR[m] = AS(k, ty * 8 + m);
#pragma unroll
            for (int n = 0; n < 8; n++) bR[n] = BS(k, tx * 8 + n);
#pragma unroll
            for (int m = 0; m < 8; m++)
#pragma unroll
                for (int n = 0; n < 8; n++)
                    acc[m][n] = fmaf(aR[m], bR[n], acc[m][n]);
        }
        __syncthreads();
    }

    float cs[8], cq[8];
    if (STATS) {
#pragma unroll
        for (int n = 0; n < 8; n++) { cs[n] = 0.f; cq[n] = 0.f; }
    }
#pragma unroll
    for (int m = 0; m < 8; m++) {
        int grow = blockRow + ty * 8 + m;
        if (grow >= M) continue;
#pragma unroll
        for (int n = 0; n < 8; n += 4) {
            int gc = tx * 8 + n;
            float4 b4 = *(const float4*)(bias + gc);
            float4 o;
            o.x = acc[m][n + 0] + b4.x;
            o.y = acc[m][n + 1] + b4.y;
            o.z = acc[m][n + 2] + b4.z;
            o.w = acc[m][n + 3] + b4.w;
            if (RELU_OUT) {
                o.x = fmaxf(o.x, 0.f); o.y = fmaxf(o.y, 0.f);
                o.z = fmaxf(o.z, 0.f); o.w = fmaxf(o.w, 0.f);
            }
            if (STATS) {
                cs[n + 0] += o.x; cq[n + 0] += o.x * o.x;
                cs[n + 1] += o.y; cq[n + 1] += o.y * o.y;
                cs[n + 2] += o.z; cq[n + 2] += o.z * o.z;
                cs[n + 3] += o.w; cq[n + 3] += o.w * o.w;
            }
            *(float4*)(C + (size_t)grow * 128 + gc) = o;
        }
    }

    if (STATS) {
        // reduce over ty (16 row-groups) in reused smem, then 1 atomicAdd set
        __syncthreads();
        float* red = sm + (tx * 16 + ty) * 16;
#pragma unroll
        for (int n = 0; n < 8; n++) { red[n] = cs[n]; red[8 + n] = cq[n]; }
        __syncthreads();
#pragma unroll
        for (int step = 8; step > 0; step >>= 1) {
            if (ty < step) {
                float* a = sm + (tx * 16 + ty) * 16;
                float* b = sm + (tx * 16 + ty + step) * 16;
#pragma unroll
                for (int j = 0; j < 16; j++) a[j] += b[j];
            }
            __syncthreads();
        }
        if (ty == 0) {
            float* a = sm + (tx * 16) * 16;
#pragma unroll
            for (int n = 0; n < 8; n++) {
                atomicAdd(&g_sum[tx * 8 + n],   a[n]);
                atomicAdd(&g_sumsq[tx * 8 + n], a[8 + n]);
            }
        }
    }
#undef AS
#undef BS
}

// ---------------- BatchNorm finalize ----------------------------------------
__global__ void bn_finalize_kernel(const float* __restrict__ g,
                                   const float* __restrict__ be) {
    int c = threadIdx.x;
    float mu  = g_sum[c] * (1.0f / N_NODES);
    float var = g_sumsq[c] * (1.0f / N_NODES) - mu * mu;
    float sc  = g[c] * rsqrtf(var + 1e-5f);
    g_scale[c] = sc;
    g_shift[c] = be[c] - mu * sc;
    g_sum[c] = 0.f;    // reset so the captured graph is replayable
    g_sumsq[c] = 0.f;
}

// ---------------- head: out[i,o] = T(row, relu'd already) @ hwb + hbb -------
__global__ void head_kernel(const float* __restrict__ W,
                            const float* __restrict__ b, float* __restrict__ out) {
    const float* T = BUF<1>();
    int gw   = (blockIdx.x * blockDim.x + threadIdx.x) >> 5;  // warp per node
    int lane = threadIdx.x & 31;
    if (gw >= N_NODES) return;
    float4 t  = ((const float4*)T)[(size_t)gw * 32 + lane];
    float4 w0 = ((const float4*)W)[lane * 2];      // (k0o0, k0o1, k1o0, k1o1)
    float4 w1 = ((const float4*)W)[lane * 2 + 1];  // (k2o0, k2o1, k3o0, k3o1)
    float a0 = t.x * w0.x + t.y * w0.z + t.z * w1.x + t.w * w1.z;
    float a1 = t.x * w0.y + t.y * w0.w + t.z * w1.y + t.w * w1.w;
#pragma unroll
    for (int o = 16; o > 0; o >>= 1) {
        a0 += __shfl_xor_sync(0xffffffffu, a0, o);
        a1 += __shfl_xor_sync(0xffffffffu, a1, o);
    }
    if (lane == 0) {
        out[(size_t)gw * 2 + 0] = a0 + b[0];
        out[(size_t)gw * 2 + 1] = a1 + b[1];
    }
}

// ---------------- launch -----------------------------------------------------
extern "C" void kernel_launch(void* const* d_in, const int* in_sizes, int n_in,
                              void* d_out, int out_size) {
    const float* x    = (const float*)d_in[0];
    const int*   ei32 = (const int*)d_in[1];   // int32 OR int64 (detected on device)
    const float* w0a = (const float*)d_in[2];
    const float* b0a = (const float*)d_in[3];
    const float* g0  = (const float*)d_in[4];
    const float* be0 = (const float*)d_in[5];
    const float* w0b = (const float*)d_in[6];
    const float* b0b = (const float*)d_in[7];
    const float* ep0 = (const float*)d_in[8];
    const float* w1a = (const float*)d_in[9];
    const float* b1a = (const float*)d_in[10];
    const float* g1  = (const float*)d_in[11];
    const float* be1 = (const float*)d_in[12];
    const float* w1b = (const float*)d_in[13];
    const float* b1b = (const float*)d_in[14];
    const float* ep1 = (const float*)d_in[15];
    const float* w2a = (const float*)d_in[16];
    const float* b2a = (const float*)d_in[17];
    const float* g2  = (const float*)d_in[18];
    const float* be2 = (const float*)d_in[19];
    const float* w2b = (const float*)d_in[20];
    const float* b2b = (const float*)d_in[21];
    const float* ep2 = (const float*)d_in[22];
    const float* hwa = (const float*)d_in[23];
    const float* hba = (const float*)d_in[24];
    const float* hwb = (const float*)d_in[25];
    const float* hbb = (const float*)d_in[26];
    float* out = (float*)d_out;

    const int edgeBlocks = (N_EDGES + 255) / 256;
    const int padBlocks  = (NPAD + 255) / 256;
    const int warpBlocks = (N_NODES * 32 + 255) / 256;  // warp-per-node kernels
    const int gemmBlocks = (N_NODES + 127) / 128;

    // CSR by dst (built once per launch; reused by all 3 layers)
    detect_kernel<<<1, 256>>>(ei32);
    init_kernel<<<padBlocks, 256>>>();
    hist_kernel<<<edgeBlocks, 256>>>(ei32);
    scan1_kernel<<<25, 1024>>>();
    scan2_kernel<<<1, 32>>>();
    scan3_kernel<<<100, 256>>>();
    fill_kernel<<<edgeBlocks, 256>>>(ei32);

    // ---- layer 0 (D_in = 64): x -> P -> Q -> P ----
    aggregate_kernel<64, -1, 0><<<warpBlocks, 256>>>(x, ep0);
    sgemm_kernel<0, 1, false, false, true><<<gemmBlocks, 256>>>(w0a, b0a, 64);
    bn_finalize_kernel<<<1, 128>>>(g0, be0);
    sgemm_kernel<1, 0, true, true, false><<<gemmBlocks, 256>>>(w0b, b0b, 128);

    // ---- layer 1: P -> Q -> P -> Q ----
    aggregate_kernel<128, 0, 1><<<warpBlocks, 256>>>(nullptr, ep1);
    sgemm_kernel<1, 0, false, false, true><<<gemmBlocks, 256>>>(w1a, b1a, 128);
    bn_finalize_kernel<<<1, 128>>>(g1, be1);
    sgemm_kernel<0, 1, true, true, false><<<gemmBlocks, 256>>>(w1b, b1b, 128);

    // ---- layer 2: Q -> P -> Q -> P ----
    aggregate_kernel<128, 1, 0><<<warpBlocks, 256>>>(nullptr, ep2);
    sgemm_kernel<0, 1, false, false, true><<<gemmBlocks, 256>>>(w2a, b2a, 128);
    bn_finalize_kernel<<<1, 128>>>(g2, be2);
    sgemm_kernel<1, 0, true, true, false><<<gemmBlocks, 256>>>(w2b, b2b, 128);

    // ---- head: relu(P@hwa+hba) -> Q; Q@hwb+hbb -> out ----
    sgemm_kernel<0, 1, false, true, false><<<gemmBlocks, 256>>>(hwa, hba, 128);
    head_kernel<<<warpBlocks, 256>>>(hwb, hbb, out);
}

// round 12
// speedup vs baseline: 2.0452x; 1.6169x over previous
#include <cuda_runtime.h>
#include <cuda_bf16.h>

#define N_NODES 100000
#define N_EDGES 1600000
#define H       128
#define NPAD    102400              // 25 * 4096, padded for guard-free int4 scan

// ---------------- scratch (device globals; no allocation allowed) ----------
__device__ __align__(16) float g_bufP[(size_t)N_NODES * H];
__device__ __align__(16) float g_bufQ[(size_t)N_NODES * H];
__device__ __align__(16) int   g_count[NPAD];        // histogram, then fill-cursor
__device__ __align__(16) int   g_off[NPAD + 4];      // CSR row offsets (padded)
__device__ int   g_part[32];                         // per-block scan partials
__device__ int   g_csr[N_EDGES];
__device__ __align__(16) float g_sum[H];
__device__ __align__(16) float g_sumsq[H];
__device__ __align__(16) float g_scale[H];
__device__ __align__(16) float g_shift[H];
__device__ int   g_is64;   // edge_index dtype flag: 1 = int64 layout, 0 = int32

// compile-time buffer selector: 0=P, 1=Q
template <int S>
__device__ __forceinline__ float* BUF() { return (S == 0) ? g_bufP : g_bufQ; }

__device__ __forceinline__ int edge_src(const int* __restrict__ ei32, int e, int is64) {
    return is64 ? ei32[2 * e] : ei32[e];
}
__device__ __forceinline__ int edge_dst(const int* __restrict__ ei32, int e, int is64) {
    return is64 ? ei32[2 * (N_EDGES + e)] : ei32[N_EDGES + e];
}

// bf16x2 split helpers: x = hi + lo, hi/lo bf16; pack pairs (x,y) into .b32
__device__ __forceinline__ void split2(float x, float y, unsigned& hi, unsigned& lo) {
    __nv_bfloat16 hx = __float2bfloat16_rn(x);
    __nv_bfloat16 hy = __float2bfloat16_rn(y);
    float rx = x - __bfloat162float(hx);
    float ry = y - __bfloat162float(hy);
    __nv_bfloat16 lx = __float2bfloat16_rn(rx);
    __nv_bfloat16 ly = __float2bfloat16_rn(ry);
    hi = ((unsigned)__bfloat16_as_ushort(hy) << 16) | __bfloat16_as_ushort(hx);
    lo = ((unsigned)__bfloat16_as_ushort(ly) << 16) | __bfloat16_as_ushort(lx);
}

__device__ __forceinline__ void mma_bf16(float* d, const unsigned* a, const unsigned* b) {
    asm volatile(
        "mma.sync.aligned.m16n8k16.row.col.f32.bf16.bf16.f32 "
        "{%0,%1,%2,%3}, {%4,%5,%6,%7}, {%8,%9}, {%0,%1,%2,%3};"
        : "+f"(d[0]), "+f"(d[1]), "+f"(d[2]), "+f"(d[3])
        : "r"(a[0]), "r"(a[1]), "r"(a[2]), "r"(a[3]), "r"(b[0]), "r"(b[1]));
}

// ---------------- dtype detect + init --------------------------------------
__global__ void detect_kernel(const int* __restrict__ ei32) {
    __shared__ int nz;
    if (threadIdx.x == 0) nz = 0;
    __syncthreads();
    int w = ei32[2 * threadIdx.x + 1];
    if (w != 0) atomicOr(&nz, 1);
    __syncthreads();
    if (threadIdx.x == 0) g_is64 = (nz == 0) ? 1 : 0;
}

__global__ void init_kernel() {
    int i = blockIdx.x * blockDim.x + threadIdx.x;
    if (i < NPAD) g_count[i] = 0;
    if (i < H) { g_sum[i] = 0.f; g_sumsq[i] = 0.f; }
}

// ---------------- CSR build -------------------------------------------------
__global__ void hist_kernel(const int* __restrict__ ei32) {
    int e = blockIdx.x * blockDim.x + threadIdx.x;
    int is64 = g_is64;
    if (e < N_EDGES) atomicAdd(&g_count[edge_dst(ei32, e, is64)], 1);
}

__global__ void scan1_kernel() {
    __shared__ int wsum[32];
    int b = blockIdx.x, t = threadIdx.x;
    int base = b * 4096 + t * 4;
    int4 v = *(const int4*)&g_count[base];
    int s0 = v.x, s1 = s0 + v.y, s2 = s1 + v.z, s3 = s2 + v.w;
    int lane = t & 31, wid = t >> 5;
    int x = s3;
#pragma unroll
    for (int o = 1; o < 32; o <<= 1) {
        int y = __shfl_up_sync(0xffffffffu, x, o);
        if (lane >= o) x += y;
    }
    if (lane == 31) wsum[wid] = x;
    __syncthreads();
    if (wid == 0) {
        int w = wsum[lane];
#pragma unroll
        for (int o = 1; o < 32; o <<= 1) {
            int y = __shfl_up_sync(0xffffffffu, w, o);
            if (lane >= o) w += y;
        }
        wsum[lane] = w;
    }
    __syncthreads();
    int warpoff = (wid == 0) ? 0 : wsum[wid - 1];
    int texc = warpoff + x - s3;
    int4 o4;
    o4.x = texc; o4.y = texc + s0; o4.z = texc + s1; o4.w = texc + s2;
    *(int4*)&g_off[base] = o4;
    if (t == 1023) g_part[b] = warpoff + x;
}

__global__ void scan2_kernel() {
    int lane = threadIdx.x;
    int v = (lane < 25) ? g_part[lane] : 0;
    int x = v;
#pragma unroll
    for (int o = 1; o < 32; o <<= 1) {
        int y = __shfl_up_sync(0xffffffffu, x, o);
        if (lane >= o) x += y;
    }
    if (lane < 25) g_part[lane] = x - v;
}

__global__ void scan3_kernel() {
    int i4 = (blockIdx.x * blockDim.x + threadIdx.x) * 4;
    int add = g_part[i4 >> 12];
    int4 v = *(const int4*)&g_off[i4];
    v.x += add; v.y += add; v.z += add; v.w += add;
    *(int4*)&g_off[i4] = v;
    *(int4*)&g_count[i4] = v;
}

__global__ void fill_kernel(const int* __restrict__ ei32) {
    int e = blockIdx.x * blockDim.x + threadIdx.x;
    int is64 = g_is64;
    if (e < N_EDGES) {
        int d = edge_dst(ei32, e, is64);
        int p = atomicAdd(&g_count[d], 1);
        g_csr[p] = edge_src(ei32, e, is64);
    }
}

// ---------------- aggregation: dst = (1+eps)*X + sum_{j in nbr} X[j] --------
template <int D, int SRCSEL, int DSTSEL>
__global__ void aggregate_kernel(const float* __restrict__ Xext,
                                 const float* __restrict__ eps_p) {
    const float* X = (SRCSEL < 0) ? Xext : BUF<(SRCSEL < 0) ? 0 : SRCSEL>();
    float* out = BUF<DSTSEL>();
    int gw   = (blockIdx.x * blockDim.x + threadIdx.x) >> 5;
    int lane = threadIdx.x & 31;
    if (gw >= N_NODES) return;
    float epsv = 1.0f + eps_p[0];
    int s = g_off[gw], e = g_off[gw + 1];
    if (D == 128) {
        float4 acc = make_float4(0.f, 0.f, 0.f, 0.f);
        const float4* Xv = (const float4*)X;
        for (int t = s; t < e; t++) {
            int j = g_csr[t];
            float4 v = Xv[(size_t)j * 32 + lane];
            acc.x += v.x; acc.y += v.y; acc.z += v.z; acc.w += v.w;
        }
        float4 xv = Xv[(size_t)gw * 32 + lane];
        float4 o;
        o.x = fmaf(epsv, xv.x, acc.x);
        o.y = fmaf(epsv, xv.y, acc.y);
        o.z = fmaf(epsv, xv.z, acc.z);
        o.w = fmaf(epsv, xv.w, acc.w);
        ((float4*)out)[(size_t)gw * 32 + lane] = o;
    } else {  // D == 64
        float2 acc = make_float2(0.f, 0.f);
        const float2* Xv = (const float2*)X;
        for (int t = s; t < e; t++) {
            int j = g_csr[t];
            float2 v = Xv[(size_t)j * 32 + lane];
            acc.x += v.x; acc.y += v.y;
        }
        float2 xv = Xv[(size_t)gw * 32 + lane];
        float2 o;
        o.x = fmaf(epsv, xv.x, acc.x);
        o.y = fmaf(epsv, xv.y, acc.y);
        ((float2*)out)[(size_t)gw * 32 + lane] = o;
    }
}

// ---------------- bf16x3 tensor-core GEMM: C[M,128] = op(A[M,K]) @ B[K,128] -
// Split-precision: A,B -> hi+lo bf16 planes; acc = Ah*Bh + Ah*Bl + Al*Bh (fp32).
// TRANS_A: BN scale/shift + relu fused on A load; STATS: col sum/sumsq of C.
// Block 128x128, 8 warps (2x4), warp tile 64x32, m16n8k16 atoms.
template <int ASEL, int CSEL, bool TRANS_A, bool RELU_OUT, bool STATS>
__global__ __launch_bounds__(256, 2)
void mma_gemm_kernel(const float* __restrict__ B,
                     const float* __restrict__ bias, int K) {
    const float* A = BUF<ASEL>();
    float* C = BUF<CSEL>();
    const int M = N_NODES;
    // k-pair-packed bf16x2 planes. A stride 12 (8 used), B stride 136 (128 used):
    // both give fully bank-conflict-free fragment LDS.
    __shared__ unsigned AsH[128 * 12];
    __shared__ unsigned AsL[128 * 12];
    __shared__ unsigned BsH[8 * 136];
    __shared__ unsigned BsL[8 * 136];
    int tid  = threadIdx.x;
    int lane = tid & 31, wid = tid >> 5;
    int warp_m = wid & 1, warp_n = wid >> 1;   // 2 x 4 warp grid
    int g = lane >> 2, t = lane & 3;
    int blockRow = blockIdx.x * 128;

    float acc[4][4][4];
#pragma unroll
    for (int i = 0; i < 4; i++)
#pragma unroll
        for (int j = 0; j < 4; j++)
#pragma unroll
            for (int q = 0; q < 4; q++) acc[i][j][q] = 0.f;

    for (int k0 = 0; k0 < K; k0 += 16) {
        // A tile: 128 rows x 16 k -> hi/lo pair-packed, row stride 12
#pragma unroll
        for (int i = 0; i < 2; i++) {
            int f = tid + i * 256;
            int r = f >> 2;
            int c = (f & 3) * 4;          // k-offset within chunk (0,4,8,12)
            int grow = blockRow + r;
            float4 v = make_float4(0.f, 0.f, 0.f, 0.f);
            if (grow < M) v = *(const float4*)(A + (size_t)grow * K + k0 + c);
            if (TRANS_A) {
                float4 sc = *(const float4*)(g_scale + k0 + c);
                float4 sh = *(const float4*)(g_shift + k0 + c);
                v.x = fmaxf(fmaf(v.x, sc.x, sh.x), 0.f);
                v.y = fmaxf(fmaf(v.y, sc.y, sh.y), 0.f);
                v.z = fmaxf(fmaf(v.z, sc.z, sh.z), 0.f);
                v.w = fmaxf(fmaf(v.w, sc.w, sh.w), 0.f);
            }
            unsigned h0, l0, h1, l1;
            split2(v.x, v.y, h0, l0);
            split2(v.z, v.w, h1, l1);
            int p = c >> 1;               // k-pair index (0..7)
            AsH[r * 12 + p]     = h0;
            AsH[r * 12 + p + 1] = h1;
            AsL[r * 12 + p]     = l0;
            AsL[r * 12 + p + 1] = l1;
        }
        // B tile: 16 k x 128 n -> pair-packed along k, row stride 136
#pragma unroll
        for (int i = 0; i < 4; i++) {
            int f = tid + i * 256;
            int p = f >> 7;               // k-pair (0..7)
            int c = f & 127;              // n
            float v0 = B[(size_t)(k0 + 2 * p) * 128 + c];
            float v1 = B[(size_t)(k0 + 2 * p + 1) * 128 + c];
            unsigned h, l;
            split2(v0, v1, h, l);
            BsH[p * 136 + c] = h;
            BsL[p * 136 + c] = l;
        }
        __syncthreads();

        unsigned ah[4][4], al[4][4];
#pragma unroll
        for (int ma = 0; ma < 4; ma++) {
            int row = warp_m * 64 + ma * 16;
            ah[ma][0] = AsH[(row + g) * 12 + t];
            ah[ma][1] = AsH[(row + g + 8) * 12 + t];
            ah[ma][2] = AsH[(row + g) * 12 + t + 4];
            ah[ma][3] = AsH[(row + g + 8) * 12 + t + 4];
            al[ma][0] = AsL[(row + g) * 12 + t];
            al[ma][1] = AsL[(row + g + 8) * 12 + t];
            al[ma][2] = AsL[(row + g) * 12 + t + 4];
            al[ma][3] = AsL[(row + g + 8) * 12 + t + 4];
        }
#pragma unroll
        for (int na = 0; na < 4; na++) {
            int col = warp_n * 32 + na * 8 + g;
            unsigned bh[2], bl[2];
            bh[0] = BsH[t * 136 + col];
            bh[1] = BsH[(t + 4) * 136 + col];
            bl[0] = BsL[t * 136 + col];
            bl[1] = BsL[(t + 4) * 136 + col];
#pragma unroll
            for (int ma = 0; ma < 4; ma++) {
                mma_bf16(acc[ma][na], ah[ma], bh);
                mma_bf16(acc[ma][na], ah[ma], bl);
                mma_bf16(acc[ma][na], al[ma], bh);
            }
        }
        __syncthreads();
    }

    // epilogue: bias (+relu) (+stats), scattered float2 stores
    float cs[4][2], cq[4][2];
    if (STATS) {
#pragma unroll
        for (int na = 0; na < 4; na++) {
            cs[na][0] = cs[na][1] = 0.f;
            cq[na][0] = cq[na][1] = 0.f;
        }
    }
#pragma unroll
    for (int na = 0; na < 4; na++) {
        int c0 = warp_n * 32 + na * 8 + 2 * t;
        float b0 = __ldg(bias + c0), b1 = __ldg(bias + c0 + 1);
#pragma unroll
        for (int ma = 0; ma < 4; ma++) {
            int r0 = blockRow + warp_m * 64 + ma * 16 + g;
            int r1 = r0 + 8;
            float v00 = acc[ma][na][0] + b0;
            float v01 = acc[ma][na][1] + b1;
            float v10 = acc[ma][na][2] + b0;
            float v11 = acc[ma][na][3] + b1;
            if (RELU_OUT) {
                v00 = fmaxf(v00, 0.f); v01 = fmaxf(v01, 0.f);
                v10 = fmaxf(v10, 0.f); v11 = fmaxf(v11, 0.f);
            }
            if (r0 < M) {
                float2 p; p.x = v00; p.y = v01;
                *(float2*)(C + (size_t)r0 * 128 + c0) = p;
                if (STATS) {
                    cs[na][0] += v00; cq[na][0] += v00 * v00;
                    cs[na][1] += v01; cq[na][1] += v01 * v01;
                }
            }
            if (r1 < M) {
                float2 p; p.x = v10; p.y = v11;
                *(float2*)(C + (size_t)r1 * 128 + c0) = p;
                if (STATS) {
                    cs[na][0] += v10; cq[na][0] += v10 * v10;
                    cs[na][1] += v11; cq[na][1] += v11 * v11;
                }
            }
        }
    }
    if (STATS) {
#pragma unroll
        for (int na = 0; na < 4; na++)
#pragma unroll
            for (int j = 0; j < 2; j++) {
                float s = cs[na][j], q = cq[na][j];
                s += __shfl_xor_sync(0xffffffffu, s, 4);
                q += __shfl_xor_sync(0xffffffffu, q, 4);
                s += __shfl_xor_sync(0xffffffffu, s, 8);
                q += __shfl_xor_sync(0xffffffffu, q, 8);
                s += __shfl_xor_sync(0xffffffffu, s, 16);
                q += __shfl_xor_sync(0xffffffffu, q, 16);
                if (lane < 4) {
                    int c = warp_n * 32 + na * 8 + 2 * t + j;
                    atomicAdd(&g_sum[c], s);
                    atomicAdd(&g_sumsq[c], q);
                }
            }
    }
}

// ---------------- BatchNorm finalize ----------------------------------------
__global__ void bn_finalize_kernel(const float* __restrict__ g,
                                   const float* __restrict__ be) {
    int c = threadIdx.x;
    float mu  = g_sum[c] * (1.0f / N_NODES);
    float var = g_sumsq[c] * (1.0f / N_NODES) - mu * mu;
    float sc  = g[c] * rsqrtf(var + 1e-5f);
    g_scale[c] = sc;
    g_shift[c] = be[c] - mu * sc;
    g_sum[c] = 0.f;
    g_sumsq[c] = 0.f;
}

// ---------------- head: out[i,o] = T(row) @ hwb + hbb -----------------------
__global__ void head_kernel(const float* __restrict__ W,
                            const float* __restrict__ b, float* __restrict__ out) {
    const float* T = BUF<1>();
    int gw   = (blockIdx.x * blockDim.x + threadIdx.x) >> 5;
    int lane = threadIdx.x & 31;
    if (gw >= N_NODES) return;
    float4 t  = ((const float4*)T)[(size_t)gw * 32 + lane];
    float4 w0 = ((const float4*)W)[lane * 2];
    float4 w1 = ((const float4*)W)[lane * 2 + 1];
    float a0 = t.x * w0.x + t.y * w0.z + t.z * w1.x + t.w * w1.z;
    float a1 = t.x * w0.y + t.y * w0.w + t.z * w1.y + t.w * w1.w;
#pragma unroll
    for (int o = 16; o > 0; o >>= 1) {
        a0 += __shfl_xor_sync(0xffffffffu, a0, o);
        a1 += __shfl_xor_sync(0xffffffffu, a1, o);
    }
    if (lane == 0) {
        out[(size_t)gw * 2 + 0] = a0 + b[0];
        out[(size_t)gw * 2 + 1] = a1 + b[1];
    }
}

// ---------------- launch -----------------------------------------------------
extern "C" void kernel_launch(void* const* d_in, const int* in_sizes, int n_in,
                              void* d_out, int out_size) {
    const float* x    = (const float*)d_in[0];
    const int*   ei32 = (const int*)d_in[1];
    const float* w0a = (const float*)d_in[2];
    const float* b0a = (const float*)d_in[3];
    const float* g0  = (const float*)d_in[4];
    const float* be0 = (const float*)d_in[5];
    const float* w0b = (const float*)d_in[6];
    const float* b0b = (const float*)d_in[7];
    const float* ep0 = (const float*)d_in[8];
    const float* w1a = (const float*)d_in[9];
    const float* b1a = (const float*)d_in[10];
    const float* g1  = (const float*)d_in[11];
    const float* be1 = (const float*)d_in[12];
    const float* w1b = (const float*)d_in[13];
    const float* b1b = (const float*)d_in[14];
    const float* ep1 = (const float*)d_in[15];
    const float* w2a = (const float*)d_in[16];
    const float* b2a = (const float*)d_in[17];
    const float* g2  = (const float*)d_in[18];
    const float* be2 = (const float*)d_in[19];
    const float* w2b = (const float*)d_in[20];
    const float* b2b = (const float*)d_in[21];
    const float* ep2 = (const float*)d_in[22];
    const float* hwa = (const float*)d_in[23];
    const float* hba = (const float*)d_in[24];
    const float* hwb = (const float*)d_in[25];
    const float* hbb = (const float*)d_in[26];
    float* out = (float*)d_out;

    const int edgeBlocks = (N_EDGES + 255) / 256;
    const int padBlocks  = (NPAD + 255) / 256;
    const int warpBlocks = (N_NODES * 32 + 255) / 256;
    const int gemmBlocks = (N_NODES + 127) / 128;

    // CSR by dst
    detect_kernel<<<1, 256>>>(ei32);
    init_kernel<<<padBlocks, 256>>>();
    hist_kernel<<<edgeBlocks, 256>>>(ei32);
    scan1_kernel<<<25, 1024>>>();
    scan2_kernel<<<1, 32>>>();
    scan3_kernel<<<100, 256>>>();
    fill_kernel<<<edgeBlocks, 256>>>(ei32);

    // ---- layer 0 (K=64): x -> P -> Q -> P ----
    aggregate_kernel<64, -1, 0><<<warpBlocks, 256>>>(x, ep0);
    mma_gemm_kernel<0, 1, false, false, true><<<gemmBlocks, 256>>>(w0a, b0a, 64);
    bn_finalize_kernel<<<1, 128>>>(g0, be0);
    mma_gemm_kernel<1, 0, true, true, false><<<gemmBlocks, 256>>>(w0b, b0b, 128);

    // ---- layer 1: P -> Q -> P -> Q ----
    aggregate_kernel<128, 0, 1><<<warpBlocks, 256>>>(nullptr, ep1);
    mma_gemm_kernel<1, 0, false, false, true><<<gemmBlocks, 256>>>(w1a, b1a, 128);
    bn_finalize_kernel<<<1, 128>>>(g1, be1);
    mma_gemm_kernel<0, 1, true, true, false><<<gemmBlocks, 256>>>(w1b, b1b, 128);

    // ---- layer 2: Q -> P -> Q -> P ----
    aggregate_kernel<128, 1, 0><<<warpBlocks, 256>>>(nullptr, ep2);
    mma_gemm_kernel<0, 1, false, false, true><<<gemmBlocks, 256>>>(w2a, b2a, 128);
    bn_finalize_kernel<<<1, 128>>>(g2, be2);
    mma_gemm_kernel<1, 0, true, true, false><<<gemmBlocks, 256>>>(w2b, b2b, 128);

    // ---- head: relu(P@hwa+hba) -> Q; Q@hwb+hbb -> out ----
    mma_gemm_kernel<0, 1, false, true, false><<<gemmBlocks, 256>>>(hwa, hba, 128);
    head_kernel<<<warpBlocks, 256>>>(hwb, hbb, out);
}

// round 16
// speedup vs baseline: 2.2276x; 1.0892x over previous
#include <cuda_runtime.h>
#include <cuda_bf16.h>

#define N_NODES 100000
#define N_EDGES 1600000
#define H       128
#define NPAD    102400              // 25 * 4096, padded for guard-free int4 scan

// ---------------- scratch (device globals; no allocation allowed) ----------
__device__ __align__(16) float g_bufP[(size_t)N_NODES * H];
__device__ __align__(16) float g_bufQ[(size_t)N_NODES * H];
__device__ __align__(16) int   g_count[NPAD];        // histogram, then fill-cursor
__device__ __align__(16) int   g_off[NPAD + 4];      // CSR row offsets (padded)
__device__ int   g_part[32];                         // per-block scan partials
__device__ int   g_csr[N_EDGES];
__device__ __align__(16) float g_sum[H];
__device__ __align__(16) float g_sumsq[H];
__device__ __align__(16) float g_scale[H];
__device__ __align__(16) float g_shift[H];
__device__ int   g_is64;   // edge_index dtype flag: 1 = int64 layout, 0 = int32

// compile-time buffer selector: 0=P, 1=Q
template <int S>
__device__ __forceinline__ float* BUF() { return (S == 0) ? g_bufP : g_bufQ; }

__device__ __forceinline__ int edge_src(const int* __restrict__ ei32, int e, int is64) {
    return is64 ? ei32[2 * e] : ei32[e];
}
__device__ __forceinline__ int edge_dst(const int* __restrict__ ei32, int e, int is64) {
    return is64 ? ei32[2 * (N_EDGES + e)] : ei32[N_EDGES + e];
}

// bf16x2 split helpers: x = hi + lo, hi/lo bf16; pack pairs (x,y) into .b32
__device__ __forceinline__ void split2(float x, float y, unsigned& hi, unsigned& lo) {
    __nv_bfloat16 hx = __float2bfloat16_rn(x);
    __nv_bfloat16 hy = __float2bfloat16_rn(y);
    float rx = x - __bfloat162float(hx);
    float ry = y - __bfloat162float(hy);
    __nv_bfloat16 lx = __float2bfloat16_rn(rx);
    __nv_bfloat16 ly = __float2bfloat16_rn(ry);
    hi = ((unsigned)__bfloat16_as_ushort(hy) << 16) | __bfloat16_as_ushort(hx);
    lo = ((unsigned)__bfloat16_as_ushort(ly) << 16) | __bfloat16_as_ushort(lx);
}

__device__ __forceinline__ void mma_bf16(float* d, const unsigned* a, const unsigned* b) {
    asm volatile(
        "mma.sync.aligned.m16n8k16.row.col.f32.bf16.bf16.f32 "
        "{%0,%1,%2,%3}, {%4,%5,%6,%7}, {%8,%9}, {%0,%1,%2,%3};"
        : "+f"(d[0]), "+f"(d[1]), "+f"(d[2]), "+f"(d[3])
        : "r"(a[0]), "r"(a[1]), "r"(a[2]), "r"(a[3]), "r"(b[0]), "r"(b[1]));
}

// ---------------- dtype detect + init --------------------------------------
__global__ void detect_kernel(const int* __restrict__ ei32) {
    __shared__ int nz;
    if (threadIdx.x == 0) nz = 0;
    __syncthreads();
    int w = ei32[2 * threadIdx.x + 1];
    if (w != 0) atomicOr(&nz, 1);
    __syncthreads();
    if (threadIdx.x == 0) g_is64 = (nz == 0) ? 1 : 0;
}

__global__ void init_kernel() {
    int i = blockIdx.x * blockDim.x + threadIdx.x;
    if (i < NPAD) g_count[i] = 0;
    if (i < H) { g_sum[i] = 0.f; g_sumsq[i] = 0.f; }
}

// ---------------- CSR build -------------------------------------------------
__global__ void hist_kernel(const int* __restrict__ ei32) {
    int e = blockIdx.x * blockDim.x + threadIdx.x;
    int is64 = g_is64;
    if (e < N_EDGES) atomicAdd(&g_count[edge_dst(ei32, e, is64)], 1);
}

__global__ void scan1_kernel() {
    __shared__ int wsum[32];
    int b = blockIdx.x, t = threadIdx.x;
    int base = b * 4096 + t * 4;
    int4 v = *(const int4*)&g_count[base];
    int s0 = v.x, s1 = s0 + v.y, s2 = s1 + v.z, s3 = s2 + v.w;
    int lane = t & 31, wid = t >> 5;
    int x = s3;
#pragma unroll
    for (int o = 1; o < 32; o <<= 1) {
        int y = __shfl_up_sync(0xffffffffu, x, o);
        if (lane >= o) x += y;
    }
    if (lane == 31) wsum[wid] = x;
    __syncthreads();
    if (wid == 0) {
        int w = wsum[lane];
#pragma unroll
        for (int o = 1; o < 32; o <<= 1) {
            int y = __shfl_up_sync(0xffffffffu, w, o);
            if (lane >= o) w += y;
        }
        wsum[lane] = w;
    }
    __syncthreads();
    int warpoff = (wid == 0) ? 0 : wsum[wid - 1];
    int texc = warpoff + x - s3;
    int4 o4;
    o4.x = texc; o4.y = texc + s0; o4.z = texc + s1; o4.w = texc + s2;
    *(int4*)&g_off[base] = o4;
    if (t == 1023) g_part[b] = warpoff + x;
}

__global__ void scan2_kernel() {
    int lane = threadIdx.x;
    int v = (lane < 25) ? g_part[lane] : 0;
    int x = v;
#pragma unroll
    for (int o = 1; o < 32; o <<= 1) {
        int y = __shfl_up_sync(0xffffffffu, x, o);
        if (lane >= o) x += y;
    }
    if (lane < 25) g_part[lane] = x - v;
}

__global__ void scan3_kernel() {
    int i4 = (blockIdx.x * blockDim.x + threadIdx.x) * 4;
    int add = g_part[i4 >> 12];
    int4 v = *(const int4*)&g_off[i4];
    v.x += add; v.y += add; v.z += add; v.w += add;
    *(int4*)&g_off[i4] = v;
    *(int4*)&g_count[i4] = v;
}

__global__ void fill_kernel(const int* __restrict__ ei32) {
    int e = blockIdx.x * blockDim.x + threadIdx.x;
    int is64 = g_is64;
    if (e < N_EDGES) {
        int d = edge_dst(ei32, e, is64);
        int p = atomicAdd(&g_count[d], 1);
        g_csr[p] = edge_src(ei32, e, is64);
    }
}

// ---------------- aggregation: dst = (1+eps)*X + sum_{j in nbr} X[j] --------
template <int D, int SRCSEL, int DSTSEL>
__global__ void aggregate_kernel(const float* __restrict__ Xext,
                                 const float* __restrict__ eps_p) {
    const float* X = (SRCSEL < 0) ? Xext : BUF<(SRCSEL < 0) ? 0 : SRCSEL>();
    float* out = BUF<DSTSEL>();
    int gw   = (blockIdx.x * blockDim.x + threadIdx.x) >> 5;
    int lane = threadIdx.x & 31;
    if (gw >= N_NODES) return;
    float epsv = 1.0f + eps_p[0];
    int s = g_off[gw], e = g_off[gw + 1];
    if (D == 128) {
        float4 acc = make_float4(0.f, 0.f, 0.f, 0.f);
        const float4* Xv = (const float4*)X;
        for (int t = s; t < e; t++) {
            int j = g_csr[t];
            float4 v = Xv[(size_t)j * 32 + lane];
            acc.x += v.x; acc.y += v.y; acc.z += v.z; acc.w += v.w;
        }
        float4 xv = Xv[(size_t)gw * 32 + lane];
        float4 o;
        o.x = fmaf(epsv, xv.x, acc.x);
        o.y = fmaf(epsv, xv.y, acc.y);
        o.z = fmaf(epsv, xv.z, acc.z);
        o.w = fmaf(epsv, xv.w, acc.w);
        ((float4*)out)[(size_t)gw * 32 + lane] = o;
    } else {  // D == 64
        float2 acc = make_float2(0.f, 0.f);
        const float2* Xv = (const float2*)X;
        for (int t = s; t < e; t++) {
            int j = g_csr[t];
            float2 v = Xv[(size_t)j * 32 + lane];
            acc.x += v.x; acc.y += v.y;
        }
        float2 xv = Xv[(size_t)gw * 32 + lane];
        float2 o;
        o.x = fmaf(epsv, xv.x, acc.x);
        o.y = fmaf(epsv, xv.y, acc.y);
        ((float2*)out)[(size_t)gw * 32 + lane] = o;
    }
}

// ---------------- bf16x3 tensor-core GEMM: C[M,128] = op(A[M,K]) @ B[K,128] -
// Split-precision: A,B -> hi+lo bf16 planes; acc = Ah*Bh + Ah*Bl + Al*Bh (fp32).
// TRANS_A: BN scale/shift + relu fused on A load; STATS: col sum/sumsq of C.
// HEAD: skip C store; compute out[row,0..1] = relu(tile+bias) @ W2 + b2 fused.
// Block 128x128, 8 warps (2x4), warp tile 64x32, m16n8k16 atoms, K-chunk 32.
template <int ASEL, int CSEL, bool TRANS_A, bool RELU_OUT, bool STATS, bool HEAD>
__global__ __launch_bounds__(256, 2)
void mma_gemm_kernel(const float* __restrict__ B,
                     const float* __restrict__ bias, int K,
                     const float* __restrict__ W2, const float* __restrict__ b2,
                     float* __restrict__ out) {
    const float* A = BUF<ASEL>();
    float* C = BUF<CSEL>();
    const int M = N_NODES;
    // k-pair-packed bf16x2 planes, K-chunk = 32 (16 pairs).
    // A stride 20, B stride 136: fragment LDS fully bank-conflict-free.
    __shared__ unsigned AsH[128 * 20];
    __shared__ unsigned AsL[128 * 20];
    __shared__ unsigned BsH[16 * 136];
    __shared__ unsigned BsL[16 * 136];
    __shared__ float red[4][128][2];   // head cross-warp reduction
    int tid  = threadIdx.x;
    int lane = tid & 31, wid = tid >> 5;
    int warp_m = wid & 1, warp_n = wid >> 1;   // 2 x 4 warp grid
    int g = lane >> 2, t = lane & 3;
    int blockRow = blockIdx.x * 128;

    float acc[4][4][4];
#pragma unroll
    for (int i = 0; i < 4; i++)
#pragma unroll
        for (int j = 0; j < 4; j++)
#pragma unroll
            for (int q = 0; q < 4; q++) acc[i][j][q] = 0.f;

    for (int k0 = 0; k0 < K; k0 += 32) {
        // A tile: 128 rows x 32 k -> hi/lo pair-packed, row stride 20
#pragma unroll
        for (int i = 0; i < 4; i++) {
            int f = tid + i * 256;
            int r = f >> 3;
            int c = (f & 7) * 4;          // k-offset within chunk (0..28)
            int grow = blockRow + r;
            float4 v = make_float4(0.f, 0.f, 0.f, 0.f);
            if (grow < M) v = *(const float4*)(A + (size_t)grow * K + k0 + c);
            if (TRANS_A) {
                float4 sc = *(const float4*)(g_scale + k0 + c);
                float4 sh = *(const float4*)(g_shift + k0 + c);
                v.x = fmaxf(fmaf(v.x, sc.x, sh.x), 0.f);
                v.y = fmaxf(fmaf(v.y, sc.y, sh.y), 0.f);
                v.z = fmaxf(fmaf(v.z, sc.z, sh.z), 0.f);
                v.w = fmaxf(fmaf(v.w, sc.w, sh.w), 0.f);
            }
            unsigned h0, l0, h1, l1;
            split2(v.x, v.y, h0, l0);
            split2(v.z, v.w, h1, l1);
            int p = c >> 1;               // k-pair index (0..15)
            AsH[r * 20 + p]     = h0;
            AsH[r * 20 + p + 1] = h1;
            AsL[r * 20 + p]     = l0;
            AsL[r * 20 + p + 1] = l1;
        }
        // B tile: 32 k x 128 n -> pair-packed along k, row stride 136
#pragma unroll
        for (int i = 0; i < 8; i++) {
            int f = tid + i * 256;
            int p = f >> 7;               // k-pair (0..15)
            int c = f & 127;              // n
            float v0 = B[(size_t)(k0 + 2 * p) * 128 + c];
            float v1 = B[(size_t)(k0 + 2 * p + 1) * 128 + c];
            unsigned h, l;
            split2(v0, v1, h, l);
            BsH[p * 136 + c] = h;
            BsL[p * 136 + c] = l;
        }
        __syncthreads();

#pragma unroll
        for (int kg = 0; kg < 2; kg++) {
            unsigned ah[4][4], al[4][4];
#pragma unroll
            for (int ma = 0; ma < 4; ma++) {
                int row = warp_m * 64 + ma * 16;
                ah[ma][0] = AsH[(row + g) * 20 + kg * 8 + t];
                ah[ma][1] = AsH[(row + g + 8) * 20 + kg * 8 + t];
                ah[ma][2] = AsH[(row + g) * 20 + kg * 8 + t + 4];
                ah[ma][3] = AsH[(row + g + 8) * 20 + kg * 8 + t + 4];
                al[ma][0] = AsL[(row + g) * 20 + kg * 8 + t];
                al[ma][1] = AsL[(row + g + 8) * 20 + kg * 8 + t];
                al[ma][2] = AsL[(row + g) * 20 + kg * 8 + t + 4];
                al[ma][3] = AsL[(row + g + 8) * 20 + kg * 8 + t + 4];
            }
#pragma unroll
            for (int na = 0; na < 4; na++) {
                int col = warp_n * 32 + na * 8 + g;
                unsigned bh[2], bl[2];
                bh[0] = BsH[(kg * 8 + t) * 136 + col];
                bh[1] = BsH[(kg * 8 + t + 4) * 136 + col];
                bl[0] = BsL[(kg * 8 + t) * 136 + col];
                bl[1] = BsL[(kg * 8 + t + 4) * 136 + col];
#pragma unroll
                for (int ma = 0; ma < 4; ma++) {
                    mma_bf16(acc[ma][na], ah[ma], bh);
                    mma_bf16(acc[ma][na], ah[ma], bl);
                    mma_bf16(acc[ma][na], al[ma], bh);
                }
            }
        }
        __syncthreads();
    }

    // ---------------- epilogue ----------------
    if (HEAD) {
        // per-thread partial dot with W2 [128,2]; relu(v+bias) applied first
        float hp[4][2][2];   // [ma][row-half][o]
#pragma unroll
        for (int ma = 0; ma < 4; ma++)
#pragma unroll
            for (int h = 0; h < 2; h++) { hp[ma][h][0] = 0.f; hp[ma][h][1] = 0.f; }
#pragma unroll
        for (int na = 0; na < 4; na++) {
            int c0 = warp_n * 32 + na * 8 + 2 * t;
            float b0 = __ldg(bias + c0), b1 = __ldg(bias + c0 + 1);
            float w00 = __ldg(W2 + c0 * 2), w01 = __ldg(W2 + c0 * 2 + 1);
            float w10 = __ldg(W2 + c0 * 2 + 2), w11 = __ldg(W2 + c0 * 2 + 3);
#pragma unroll
            for (int ma = 0; ma < 4; ma++) {
                float v00 = fmaxf(acc[ma][na][0] + b0, 0.f);
                float v01 = fmaxf(acc[ma][na][1] + b1, 0.f);
                float v10 = fmaxf(acc[ma][na][2] + b0, 0.f);
                float v11 = fmaxf(acc[ma][na][3] + b1, 0.f);
                hp[ma][0][0] += v00 * w00 + v01 * w10;
                hp[ma][0][1] += v00 * w01 + v01 * w11;
                hp[ma][1][0] += v10 * w00 + v11 * w10;
                hp[ma][1][1] += v10 * w01 + v11 * w11;
            }
        }
        // quad-reduce over t (lanes g*4 .. g*4+3)
#pragma unroll
        for (int ma = 0; ma < 4; ma++)
#pragma unroll
            for (int h = 0; h < 2; h++)
#pragma unroll
                for (int o = 0; o < 2; o++) {
                    float s = hp[ma][h][o];
                    s += __shfl_xor_sync(0xffffffffu, s, 1);
                    s += __shfl_xor_sync(0xffffffffu, s, 2);
                    hp[ma][h][o] = s;
                }
        if (t == 0) {
#pragma unroll
            for (int ma = 0; ma < 4; ma++)
#pragma unroll
                for (int h = 0; h < 2; h++) {
                    int lrow = warp_m * 64 + ma * 16 + h * 8 + g;
                    red[warp_n][lrow][0] = hp[ma][h][0];
                    red[warp_n][lrow][1] = hp[ma][h][1];
                }
        }
        __syncthreads();
        int lrow = tid >> 1, o = tid & 1;
        int grow = blockRow + lrow;
        if (grow < M) {
            float s = red[0][lrow][o] + red[1][lrow][o] +
                      red[2][lrow][o] + red[3][lrow][o];
            out[(size_t)grow * 2 + o] = s + __ldg(b2 + o);
        }
        return;
    }

    // standard epilogue: bias (+relu) (+stats), scattered float2 stores
    float cs[4][2], cq[4][2];
    if (STATS) {
#pragma unroll
        for (int na = 0; na < 4; na++) {
            cs[na][0] = cs[na][1] = 0.f;
            cq[na][0] = cq[na][1] = 0.f;
        }
    }
#pragma unroll
    for (int na = 0; na < 4; na++) {
        int c0 = warp_n * 32 + na * 8 + 2 * t;
        float b0 = __ldg(bias + c0), b1 = __ldg(bias + c0 + 1);
#pragma unroll
        for (int ma = 0; ma < 4; ma++) {
            int r0 = blockRow + warp_m * 64 + ma * 16 + g;
            int r1 = r0 + 8;
            float v00 = acc[ma][na][0] + b0;
            float v01 = acc[ma][na][1] + b1;
            float v10 = acc[ma][na][2] + b0;
            float v11 = acc[ma][na][3] + b1;
            if (RELU_OUT) {
                v00 = fmaxf(v00, 0.f); v01 = fmaxf(v01, 0.f);
                v10 = fmaxf(v10, 0.f); v11 = fmaxf(v11, 0.f);
            }
            if (r0 < M) {
                float2 p; p.x = v00; p.y = v01;
                *(float2*)(C + (size_t)r0 * 128 + c0) = p;
                if (STATS) {
                    cs[na][0] += v00; cq[na][0] += v00 * v00;
                    cs[na][1] += v01; cq[na][1] += v01 * v01;
                }
            }
            if (r1 < M) {
                float2 p; p.x = v10; p.y = v11;
                *(float2*)(C + (size_t)r1 * 128 + c0) = p;
                if (STATS) {
                    cs[na][0] += v10; cq[na][0] += v10 * v10;
                    cs[na][1] += v11; cq[na][1] += v11 * v11;
                }
            }
        }
    }
    if (STATS) {
#pragma unroll
        for (int na = 0; na < 4; na++)
#pragma unroll
            for (int j = 0; j < 2; j++) {
                float s = cs[na][j], q = cq[na][j];
                s += __shfl_xor_sync(0xffffffffu, s, 4);
                q += __shfl_xor_sync(0xffffffffu, q, 4);
                s += __shfl_xor_sync(0xffffffffu, s, 8);
                q += __shfl_xor_sync(0xffffffffu, q, 8);
                s += __shfl_xor_sync(0xffffffffu, s, 16);
                q += __shfl_xor_sync(0xffffffffu, q, 16);
                if (lane < 4) {
                    int c = warp_n * 32 + na * 8 + 2 * t + j;
                    atomicAdd(&g_sum[c], s);
                    atomicAdd(&g_sumsq[c], q);
                }
            }
    }
}

// ---------------- BatchNorm finalize ----------------------------------------
__global__ void bn_finalize_kernel(const float* __restrict__ g,
                                   const float* __restrict__ be) {
    int c = threadIdx.x;
    float mu  = g_sum[c] * (1.0f / N_NODES);
    float var = g_sumsq[c] * (1.0f / N_NODES) - mu * mu;
    float sc  = g[c] * rsqrtf(var + 1e-5f);
    g_scale[c] = sc;
    g_shift[c] = be[c] - mu * sc;
    g_sum[c] = 0.f;
    g_sumsq[c] = 0.f;
}

// ---------------- launch -----------------------------------------------------
extern "C" void kernel_launch(void* const* d_in, const int* in_sizes, int n_in,
                              void* d_out, int out_size) {
    const float* x    = (const float*)d_in[0];
    const int*   ei32 = (const int*)d_in[1];
    const float* w0a = (const float*)d_in[2];
    const float* b0a = (const float*)d_in[3];
    const float* g0  = (const float*)d_in[4];
    const float* be0 = (const float*)d_in[5];
    const float* w0b = (const float*)d_in[6];
    const float* b0b = (const float*)d_in[7];
    const float* ep0 = (const float*)d_in[8];
    const float* w1a = (const float*)d_in[9];
    const float* b1a = (const float*)d_in[10];
    const float* g1  = (const float*)d_in[11];
    const float* be1 = (const float*)d_in[12];
    const float* w1b = (const float*)d_in[13];
    const float* b1b = (const float*)d_in[14];
    const float* ep1 = (const float*)d_in[15];
    const float* w2a = (const float*)d_in[16];
    const float* b2a = (const float*)d_in[17];
    const float* g2  = (const float*)d_in[18];
    const float* be2 = (const float*)d_in[19];
    const float* w2b = (const float*)d_in[20];
    const float* b2b = (const float*)d_in[21];
    const float* ep2 = (const float*)d_in[22];
    const float* hwa = (const float*)d_in[23];
    const float* hba = (const float*)d_in[24];
    const float* hwb = (const float*)d_in[25];
    const float* hbb = (const float*)d_in[26];
    float* out = (float*)d_out;

    const int edgeBlocks = (N_EDGES + 255) / 256;
    const int padBlocks  = (NPAD + 255) / 256;
    const int warpBlocks = (N_NODES * 32 + 255) / 256;
    const int gemmBlocks = (N_NODES + 127) / 128;

    // CSR by dst
    detect_kernel<<<1, 256>>>(ei32);
    init_kernel<<<padBlocks, 256>>>();
    hist_kernel<<<edgeBlocks, 256>>>(ei32);
    scan1_kernel<<<25, 1024>>>();
    scan2_kernel<<<1, 32>>>();
    scan3_kernel<<<100, 256>>>();
    fill_kernel<<<edgeBlocks, 256>>>(ei32);

    // ---- layer 0 (K=64): x -> P -> Q -> P ----
    aggregate_kernel<64, -1, 0><<<warpBlocks, 256>>>(x, ep0);
    mma_gemm_kernel<0, 1, false, false, true, false><<<gemmBlocks, 256>>>(
        w0a, b0a, 64, nullptr, nullptr, nullptr);
    bn_finalize_kernel<<<1, 128>>>(g0, be0);
    mma_gemm_kernel<1, 0, true, true, false, false><<<gemmBlocks, 256>>>(
        w0b, b0b, 128, nullptr, nullptr, nullptr);

    // ---- layer 1: P -> Q -> P -> Q ----
    aggregate_kernel<128, 0, 1><<<warpBlocks, 256>>>(nullptr, ep1);
    mma_gemm_kernel<1, 0, false, false, true, false><<<gemmBlocks, 256>>>(
        w1a, b1a, 128, nullptr, nullptr, nullptr);
    bn_finalize_kernel<<<1, 128>>>(g1, be1);
    mma_gemm_kernel<0, 1, true, true, false, false><<<gemmBlocks, 256>>>(
        w1b, b1b, 128, nullptr, nullptr, nullptr);

    // ---- layer 2: Q -> P -> Q -> P ----
    aggregate_kernel<128, 1, 0><<<warpBlocks, 256>>>(nullptr, ep2);
    mma_gemm_kernel<0, 1, false, false, true, false><<<gemmBlocks, 256>>>(
        w2a, b2a, 128, nullptr, nullptr, nullptr);
    bn_finalize_kernel<<<1, 128>>>(g2, be2);
    mma_gemm_kernel<1, 0, true, true, false, false><<<gemmBlocks, 256>>>(
        w2b, b2b, 128, nullptr, nullptr, nullptr);

    // ---- head fused: out = relu(P@hwa+hba) @ hwb + hbb ----
    mma_gemm_kernel<0, 1, false, true, false, true><<<gemmBlocks, 256>>>(
        hwa, hba, 128, hwb, hbb, out);
}